// round 1
// baseline (speedup 1.0000x reference)
#include <cuda_runtime.h>
#include <math.h>

// Problem constants
constexpr int Bdim = 4;
constexpr int Tdim = 96;
constexpr int Ndim = 512;
constexpr int Hdim = 128;
constexpr int Mrows = Bdim * Tdim * Ndim;   // 196608
constexpr int Kdim = Hdim;                   // 128

// Scratch (allocation-free rule: use __device__ globals)
__device__ float g_expanded[(size_t)Mrows * 2 * Hdim];  // [M, 256]
__device__ float g_gated[(size_t)Mrows * Hdim];         // [M, 128]

// C[m,o] = sum_h A[m,h] * W[o,h] + bias[o]
// A: [M,K] row-major, W: [O,K] row-major (so B^T form), C: [M,O]
template <int BM, int BN, int BK, int TM, int TN, int K>
__global__ __launch_bounds__((BM / TM) * (BN / TN))
void sgemm_wt_bias(const float* __restrict__ A,
                   const float* __restrict__ W,
                   const float* __restrict__ bias,
                   float* __restrict__ C,
                   int O)
{
    constexpr int THREADS = (BM / TM) * (BN / TN);
    __shared__ float As[BK][BM];  // K-major for vector frag loads
    __shared__ float Bs[BK][BN];

    const int tid  = threadIdx.x;
    const int bm0  = blockIdx.x * BM;
    const int bn0  = blockIdx.y * BN;
    const int trow = tid / (BN / TN);
    const int tcol = tid % (BN / TN);

    float acc[TM][TN];
#pragma unroll
    for (int i = 0; i < TM; ++i)
#pragma unroll
        for (int j = 0; j < TN; ++j) acc[i][j] = 0.0f;

    constexpr int A_F4_PER_THREAD = (BM * BK) / (4 * THREADS);
    constexpr int B_F4_PER_THREAD = (BN * BK) / (4 * THREADS);

#pragma unroll 1
    for (int kc = 0; kc < K; kc += BK) {
        // Stage A tile transposed: As[k][m]
#pragma unroll
        for (int i = 0; i < A_F4_PER_THREAD; ++i) {
            int idx = tid + i * THREADS;          // float4 index
            int row = idx / (BK / 4);
            int kq  = idx % (BK / 4);
            float4 v = *reinterpret_cast<const float4*>(
                &A[(size_t)(bm0 + row) * K + kc + kq * 4]);
            As[kq * 4 + 0][row] = v.x;
            As[kq * 4 + 1][row] = v.y;
            As[kq * 4 + 2][row] = v.z;
            As[kq * 4 + 3][row] = v.w;
        }
        // Stage W tile transposed: Bs[k][o]
#pragma unroll
        for (int i = 0; i < B_F4_PER_THREAD; ++i) {
            int idx = tid + i * THREADS;
            int orow = idx / (BK / 4);
            int kq   = idx % (BK / 4);
            float4 v = *reinterpret_cast<const float4*>(
                &W[(size_t)(bn0 + orow) * K + kc + kq * 4]);
            Bs[kq * 4 + 0][orow] = v.x;
            Bs[kq * 4 + 1][orow] = v.y;
            Bs[kq * 4 + 2][orow] = v.z;
            Bs[kq * 4 + 3][orow] = v.w;
        }
        __syncthreads();

#pragma unroll
        for (int k = 0; k < BK; ++k) {
            float4 a0 = *reinterpret_cast<const float4*>(&As[k][trow * TM]);
            float4 a1 = *reinterpret_cast<const float4*>(&As[k][trow * TM + 4]);
            float4 b0 = *reinterpret_cast<const float4*>(&Bs[k][tcol * TN]);
            float4 b1 = *reinterpret_cast<const float4*>(&Bs[k][tcol * TN + 4]);
            float a[TM] = {a0.x, a0.y, a0.z, a0.w, a1.x, a1.y, a1.z, a1.w};
            float b[TN] = {b0.x, b0.y, b0.z, b0.w, b1.x, b1.y, b1.z, b1.w};
#pragma unroll
            for (int i = 0; i < TM; ++i)
#pragma unroll
                for (int j = 0; j < TN; ++j)
                    acc[i][j] = fmaf(a[i], b[j], acc[i][j]);
        }
        __syncthreads();
    }

    // Epilogue: add bias, vector store
    float br[TN];
#pragma unroll
    for (int j = 0; j < TN; ++j) br[j] = bias[bn0 + tcol * TN + j];

#pragma unroll
    for (int i = 0; i < TM; ++i) {
        int row = bm0 + trow * TM + i;
        float4 o0, o1;
        o0.x = acc[i][0] + br[0]; o0.y = acc[i][1] + br[1];
        o0.z = acc[i][2] + br[2]; o0.w = acc[i][3] + br[3];
        o1.x = acc[i][4] + br[4]; o1.y = acc[i][5] + br[5];
        o1.z = acc[i][6] + br[6]; o1.w = acc[i][7] + br[7];
        float* cp = &C[(size_t)row * O + bn0 + tcol * TN];
        *reinterpret_cast<float4*>(cp)     = o0;
        *reinterpret_cast<float4*>(cp + 4) = o1;
    }
}

// One thread per (b, n, h) chain: EMA over T, sigmoid gate, multiply primary.
// expanded layout: [B, T, N, 2H]; output gated: [B, T, N, H]
__global__ __launch_bounds__(256)
void ema_gate_kernel(const float* __restrict__ expanded,
                     float* __restrict__ gated)
{
    int tid = blockIdx.x * blockDim.x + threadIdx.x;  // 0 .. B*N*H-1
    int h = tid & (Hdim - 1);
    int n = (tid >> 7) & (Ndim - 1);
    int b = tid >> 16;  // H*N = 65536 = 2^16

    size_t base   = (((size_t)b * Tdim) * Ndim + n) * (2 * Hdim);
    size_t stride = (size_t)Ndim * (2 * Hdim);
    size_t ybase  = (((size_t)b * Tdim) * Ndim + n) * Hdim;
    size_t ystr   = (size_t)Ndim * Hdim;

    float s = 0.0f;
#pragma unroll 4
    for (int t = 0; t < Tdim; ++t) {
        float g = expanded[base + Hdim + h];
        float p = expanded[base + h];
        s = fmaf(0.9f, s, 0.1f * g);
        float sig = 1.0f / (1.0f + expf(-s));
        gated[ybase + h] = p * sig;
        base  += stride;
        ybase += ystr;
    }
}

extern "C" void kernel_launch(void* const* d_in, const int* in_sizes, int n_in,
                              void* d_out, int out_size)
{
    const float* x     = (const float*)d_in[0];  // [B,T,N,H]
    const float* W_exp = (const float*)d_in[1];  // [2H,H]
    const float* b_exp = (const float*)d_in[2];  // [2H]
    const float* W_con = (const float*)d_in[3];  // [H,H]
    const float* b_con = (const float*)d_in[4];  // [H]
    float* out = (float*)d_out;                  // [B,T,N,H]

    float* expanded;
    float* gated;
    cudaGetSymbolAddress((void**)&expanded, g_expanded);
    cudaGetSymbolAddress((void**)&gated, g_gated);

    // GEMM1: [M,128] x [256,128]^T -> [M,256]
    {
        dim3 grid(Mrows / 128, (2 * Hdim) / 128);
        sgemm_wt_bias<128, 128, 16, 8, 8, Kdim><<<grid, 256>>>(
            x, W_exp, b_exp, expanded, 2 * Hdim);
    }

    // EMA scan + sigmoid gate + multiply primary
    {
        int total = Bdim * Ndim * Hdim;  // 262144
        ema_gate_kernel<<<total / 256, 256>>>(expanded, gated);
    }

    // GEMM2: [M,128] x [128,128]^T -> [M,128]
    {
        dim3 grid(Mrows / 128, Hdim / 128);
        sgemm_wt_bias<128, 128, 16, 8, 8, Kdim><<<grid, 256>>>(
            gated, W_con, b_con, out, Hdim);
    }
}

// round 3
// speedup vs baseline: 1.9220x; 1.9220x over previous
#include <cuda_runtime.h>
#include <cuda_bf16.h>
#include <cstdint>
#include <math.h>

// ---------------- problem constants ----------------
constexpr int Bdim = 4;
constexpr int Tdim = 96;
constexpr int Ndim = 512;
constexpr int Hdim = 128;
constexpr int Mrows = Bdim * Tdim * Ndim;   // 196608

// scratch (allocation-free rule)
__device__ float g_expanded[(size_t)Mrows * 2 * Hdim];  // [M, 256]
__device__ float g_gated[(size_t)Mrows * Hdim];         // [M, 128]

// ---------------- helpers ----------------
__device__ __forceinline__ uint32_t smem_u32(const void* p) {
    uint32_t a;
    asm("{ .reg .u64 t; cvta.to.shared.u64 t, %1; cvt.u32.u64 %0, t; }"
        : "=r"(a) : "l"(p));
    return a;
}

#define LDSM4(r, addr)                                                        \
    asm volatile("ldmatrix.sync.aligned.m8n8.x4.shared.b16 {%0,%1,%2,%3}, [%4];" \
                 : "=r"((r)[0]), "=r"((r)[1]), "=r"((r)[2]), "=r"((r)[3])     \
                 : "r"(addr))

#define MMA16816(d, a, b0, b1)                                                \
    asm volatile("mma.sync.aligned.m16n8k16.row.col.f32.bf16.bf16.f32 "       \
                 "{%0,%1,%2,%3}, {%4,%5,%6,%7}, {%8,%9}, {%0,%1,%2,%3};"      \
                 : "+f"((d)[0]), "+f"((d)[1]), "+f"((d)[2]), "+f"((d)[3])     \
                 : "r"((a)[0]), "r"((a)[1]), "r"((a)[2]), "r"((a)[3]),        \
                   "r"(b0), "r"(b1))

// fp32 [128,128] row-major tile -> (hi, lo) bf16 tiles in smem, row stride 136
constexpr int LDS_STRIDE = 136;  // 128 + 8 bf16 pad (16B) -> conflict-free ldmatrix
__device__ __forceinline__ void convert_tile(const float* __restrict__ src,
                                             __nv_bfloat16* __restrict__ hi,
                                             __nv_bfloat16* __restrict__ lo,
                                             int tid) {
#pragma unroll
    for (int it = 0; it < 16; ++it) {
        int i  = tid + it * 256;       // float4 index, 4096 total
        int r  = i >> 5;               // 32 float4 per row
        int c4 = (i & 31) << 2;
        float4 v = *reinterpret_cast<const float4*>(src + (size_t)r * 128 + c4);

        __nv_bfloat162 h0 = __float22bfloat162_rn(make_float2(v.x, v.y));
        __nv_bfloat162 h1 = __float22bfloat162_rn(make_float2(v.z, v.w));
        float2 h0f = __bfloat1622float2(h0);
        float2 h1f = __bfloat1622float2(h1);
        __nv_bfloat162 l0 = __float22bfloat162_rn(make_float2(v.x - h0f.x, v.y - h0f.y));
        __nv_bfloat162 l1 = __float22bfloat162_rn(make_float2(v.z - h1f.x, v.w - h1f.y));

        int off = r * LDS_STRIDE + c4;
        uint2 hp, lp;
        hp.x = *reinterpret_cast<uint32_t*>(&h0);
        hp.y = *reinterpret_cast<uint32_t*>(&h1);
        lp.x = *reinterpret_cast<uint32_t*>(&l0);
        lp.y = *reinterpret_cast<uint32_t*>(&l1);
        *reinterpret_cast<uint2*>(hi + off) = hp;
        *reinterpret_cast<uint2*>(lo + off) = lp;
    }
}

// ---------------- tensor-core GEMM ----------------
// C[m, o] = sum_h A[m,h] * W[o,h] + bias[o]
// A: [M,128] rm, W: [NT,128] rm (= col-major K x NT for mma ".col"), C: [M,NT]
// Grid: (M/128, NT/128). Block: 256 (8 warps, each 64x32 of the 128x128 tile).
template <int NT>
__global__ __launch_bounds__(256, 1)
void mma_gemm(const float* __restrict__ A, const float* __restrict__ W,
              const float* __restrict__ bias, float* __restrict__ C) {
    extern __shared__ char smem[];
    __nv_bfloat16* sAhi = reinterpret_cast<__nv_bfloat16*>(smem);
    __nv_bfloat16* sAlo = sAhi + 128 * LDS_STRIDE;
    __nv_bfloat16* sWhi = sAlo + 128 * LDS_STRIDE;
    __nv_bfloat16* sWlo = sWhi + 128 * LDS_STRIDE;

    const int tid  = threadIdx.x;
    const int wid  = tid >> 5;
    const int lane = tid & 31;
    const int bm0  = blockIdx.x * 128;
    const int bn0  = blockIdx.y * 128;

    convert_tile(A + (size_t)bm0 * 128, sAhi, sAlo, tid);
    convert_tile(W + (size_t)bn0 * 128, sWhi, sWlo, tid);
    __syncthreads();

    const int m0 = (wid & 1) * 64;   // warp row offset in tile
    const int n0 = (wid >> 1) * 32;  // warp col offset in tile

    float acc[4][4][4];
#pragma unroll
    for (int i = 0; i < 4; ++i)
#pragma unroll
        for (int j = 0; j < 4; ++j)
#pragma unroll
            for (int q = 0; q < 4; ++q) acc[i][j][q] = 0.0f;

    // ldmatrix lane addresses (bytes), k-step adds kk*32B (16 bf16)
    uint32_t aHi[4], aLo[4], bHi[2], bLo[2];
    {
        const uint32_t aBaseHi = smem_u32(sAhi), aBaseLo = smem_u32(sAlo);
        const uint32_t bBaseHi = smem_u32(sWhi), bBaseLo = smem_u32(sWlo);
        int ar = m0 + (lane & 15);
        int ac = (lane >> 4) * 8;
#pragma unroll
        for (int i = 0; i < 4; ++i) {
            uint32_t off = ((ar + 16 * i) * LDS_STRIDE + ac) * 2;
            aHi[i] = aBaseHi + off;
            aLo[i] = aBaseLo + off;
        }
        int br = n0 + ((lane >> 4) << 3) + (lane & 7);
        int bc = ((lane >> 3) & 1) * 8;
#pragma unroll
        for (int j = 0; j < 2; ++j) {
            uint32_t off = ((br + 16 * j) * LDS_STRIDE + bc) * 2;
            bHi[j] = bBaseHi + off;
            bLo[j] = bBaseLo + off;
        }
    }

#pragma unroll
    for (int kk = 0; kk < 8; ++kk) {
        const uint32_t ko = kk * 32;  // 16 bf16 = 32 bytes
        uint32_t ah[4][4], al[4][4], bh[2][4], bl[2][4];
#pragma unroll
        for (int i = 0; i < 4; ++i) { LDSM4(ah[i], aHi[i] + ko); }
#pragma unroll
        for (int j = 0; j < 2; ++j) { LDSM4(bh[j], bHi[j] + ko); }
#pragma unroll
        for (int i = 0; i < 4; ++i) { LDSM4(al[i], aLo[i] + ko); }
#pragma unroll
        for (int j = 0; j < 2; ++j) { LDSM4(bl[j], bLo[j] + ko); }

#pragma unroll
        for (int i = 0; i < 4; ++i) {
#pragma unroll
            for (int jj = 0; jj < 4; ++jj) {
                const int pr = jj >> 1, wh = (jj & 1) * 2;
                MMA16816(acc[i][jj], ah[i], bh[pr][wh], bh[pr][wh + 1]);  // hi*hi
                MMA16816(acc[i][jj], ah[i], bl[pr][wh], bl[pr][wh + 1]);  // hi*lo
                MMA16816(acc[i][jj], al[i], bh[pr][wh], bh[pr][wh + 1]);  // lo*hi
            }
        }
    }

    // epilogue: bias + direct float2 stores
    const int gr = lane >> 2;
    const int gc = (lane & 3) * 2;
#pragma unroll
    for (int jj = 0; jj < 4; ++jj) {
        const int col = bn0 + n0 + jj * 8 + gc;
        const float b0v = bias[col];
        const float b1v = bias[col + 1];
#pragma unroll
        for (int i = 0; i < 4; ++i) {
            const int row = bm0 + m0 + i * 16 + gr;
            float2 o0, o1;
            o0.x = acc[i][jj][0] + b0v; o0.y = acc[i][jj][1] + b1v;
            o1.x = acc[i][jj][2] + b0v; o1.y = acc[i][jj][3] + b1v;
            *reinterpret_cast<float2*>(&C[(size_t)row * NT + col])       = o0;
            *reinterpret_cast<float2*>(&C[(size_t)(row + 8) * NT + col]) = o1;
        }
    }
}

// ---------------- EMA scan + sigmoid gate (one thread per (b,n,h) chain) ----------------
__global__ __launch_bounds__(256)
void ema_gate_kernel(const float* __restrict__ expanded, float* __restrict__ gated) {
    int tid = blockIdx.x * blockDim.x + threadIdx.x;  // 0 .. B*N*H-1
    int h = tid & (Hdim - 1);
    int n = (tid >> 7) & (Ndim - 1);
    int b = tid >> 16;  // N*H = 65536

    size_t base   = (((size_t)b * Tdim) * Ndim + n) * (2 * Hdim);
    size_t stride = (size_t)Ndim * (2 * Hdim);
    size_t ybase  = (((size_t)b * Tdim) * Ndim + n) * Hdim;
    size_t ystr   = (size_t)Ndim * Hdim;

    float s = 0.0f;
#pragma unroll 4
    for (int t = 0; t < Tdim; ++t) {
        float g = expanded[base + Hdim + h];
        float p = expanded[base + h];
        s = fmaf(0.9f, s, 0.1f * g);
        float sig = 1.0f / (1.0f + __expf(-s));
        gated[ybase + h] = p * sig;
        base  += stride;
        ybase += ystr;
    }
}

// ---------------- launch ----------------
extern "C" void kernel_launch(void* const* d_in, const int* in_sizes, int n_in,
                              void* d_out, int out_size) {
    const float* x     = (const float*)d_in[0];  // [B,T,N,H]
    const float* W_exp = (const float*)d_in[1];  // [2H,H]
    const float* b_exp = (const float*)d_in[2];  // [2H]
    const float* W_con = (const float*)d_in[3];  // [H,H]
    const float* b_con = (const float*)d_in[4];  // [H]
    float* out = (float*)d_out;                  // [B,T,N,H]

    float *expanded, *gated;
    cudaGetSymbolAddress((void**)&expanded, g_expanded);
    cudaGetSymbolAddress((void**)&gated, g_gated);

    constexpr int SMEM = 4 * 128 * LDS_STRIDE * 2;  // 139264 bytes
    cudaFuncSetAttribute(mma_gemm<256>, cudaFuncAttributeMaxDynamicSharedMemorySize, SMEM);
    cudaFuncSetAttribute(mma_gemm<128>, cudaFuncAttributeMaxDynamicSharedMemorySize, SMEM);

    // GEMM1: expanded[M,256] = x[M,128] * W_exp^T + b_exp
    {
        dim3 grid(Mrows / 128, 2);
        mma_gemm<256><<<grid, 256, SMEM>>>(x, W_exp, b_exp, expanded);
    }

    // EMA scan + sigmoid gate + primary multiply
    ema_gate_kernel<<<(Bdim * Ndim * Hdim) / 256, 256>>>(expanded, gated);

    // GEMM2: out[M,128] = gated[M,128] * W_con^T + b_con
    {
        dim3 grid(Mrows / 128, 1);
        mma_gemm<128><<<grid, 256, SMEM>>>(gated, W_con, b_con, out);
    }
}

// round 4
// speedup vs baseline: 1.9508x; 1.0150x over previous
#include <cuda_runtime.h>
#include <cuda_bf16.h>
#include <cstdint>
#include <math.h>

// ---------------- problem constants ----------------
constexpr int Bdim = 4;
constexpr int Tdim = 96;
constexpr int Ndim = 512;
constexpr int Hdim = 128;
constexpr int Mrows = Bdim * Tdim * Ndim;   // 196608

// scratch (allocation-free rule)
__device__ float g_expanded[(size_t)Mrows * 2 * Hdim];  // [M, 256]
__device__ float g_gated[(size_t)Mrows * Hdim];         // [M, 128]

// ---------------- helpers ----------------
__device__ __forceinline__ uint32_t smem_u32(const void* p) {
    uint32_t a;
    asm("{ .reg .u64 t; cvta.to.shared.u64 t, %1; cvt.u32.u64 %0, t; }"
        : "=r"(a) : "l"(p));
    return a;
}

#define LDSM4(r, addr)                                                        \
    asm volatile("ldmatrix.sync.aligned.m8n8.x4.shared.b16 {%0,%1,%2,%3}, [%4];" \
                 : "=r"((r)[0]), "=r"((r)[1]), "=r"((r)[2]), "=r"((r)[3])     \
                 : "r"(addr))

#define MMA16816(d, a, b0, b1)                                                \
    asm volatile("mma.sync.aligned.m16n8k16.row.col.f32.bf16.bf16.f32 "       \
                 "{%0,%1,%2,%3}, {%4,%5,%6,%7}, {%8,%9}, {%0,%1,%2,%3};"      \
                 : "+f"((d)[0]), "+f"((d)[1]), "+f"((d)[2]), "+f"((d)[3])     \
                 : "r"((a)[0]), "r"((a)[1]), "r"((a)[2]), "r"((a)[3]),        \
                   "r"(b0), "r"(b1))

// fp32 [128,128] row-major tile -> (hi, lo) bf16 tiles in smem, row stride 136
constexpr int LDS_STRIDE = 136;  // 128 + 8 bf16 pad (16B) -> conflict-free ldmatrix
__device__ __forceinline__ void convert_tile(const float* __restrict__ src,
                                             __nv_bfloat16* __restrict__ hi,
                                             __nv_bfloat16* __restrict__ lo,
                                             int tid) {
#pragma unroll
    for (int it = 0; it < 8; ++it) {
        int i  = tid + it * 512;       // float4 index, 4096 total
        int r  = i >> 5;               // 32 float4 per row
        int c4 = (i & 31) << 2;
        float4 v = *reinterpret_cast<const float4*>(src + (size_t)r * 128 + c4);

        __nv_bfloat162 h0 = __float22bfloat162_rn(make_float2(v.x, v.y));
        __nv_bfloat162 h1 = __float22bfloat162_rn(make_float2(v.z, v.w));
        float2 h0f = __bfloat1622float2(h0);
        float2 h1f = __bfloat1622float2(h1);
        __nv_bfloat162 l0 = __float22bfloat162_rn(make_float2(v.x - h0f.x, v.y - h0f.y));
        __nv_bfloat162 l1 = __float22bfloat162_rn(make_float2(v.z - h1f.x, v.w - h1f.y));

        int off = r * LDS_STRIDE + c4;
        uint2 hp, lp;
        hp.x = *reinterpret_cast<uint32_t*>(&h0);
        hp.y = *reinterpret_cast<uint32_t*>(&h1);
        lp.x = *reinterpret_cast<uint32_t*>(&l0);
        lp.y = *reinterpret_cast<uint32_t*>(&l1);
        *reinterpret_cast<uint2*>(hi + off) = hp;
        *reinterpret_cast<uint2*>(lo + off) = lp;
    }
}

// ---------------- tensor-core GEMM ----------------
// C[m, o] = sum_h A[m,h] * W[o,h] + bias[o]
// A: [M,128] rm, W: [NT,128] rm (= col-major for mma ".col"), C: [M,NT]
// Grid: (M/128, NT/128). Block: 512 (16 warps, each 32x32 of the 128x128 tile).
template <int NT>
__global__ __launch_bounds__(512, 1)
void mma_gemm(const float* __restrict__ A, const float* __restrict__ W,
              const float* __restrict__ bias, float* __restrict__ C) {
    extern __shared__ char smem[];
    __nv_bfloat16* sAhi = reinterpret_cast<__nv_bfloat16*>(smem);
    __nv_bfloat16* sAlo = sAhi + 128 * LDS_STRIDE;
    __nv_bfloat16* sWhi = sAlo + 128 * LDS_STRIDE;
    __nv_bfloat16* sWlo = sWhi + 128 * LDS_STRIDE;

    const int tid  = threadIdx.x;
    const int wid  = tid >> 5;
    const int lane = tid & 31;
    const int bm0  = blockIdx.x * 128;
    const int bn0  = blockIdx.y * 128;

    convert_tile(A + (size_t)bm0 * 128, sAhi, sAlo, tid);
    convert_tile(W + (size_t)bn0 * 128, sWhi, sWlo, tid);
    __syncthreads();

    const int m0 = (wid & 3) * 32;   // warp row offset in tile
    const int n0 = (wid >> 2) * 32;  // warp col offset in tile

    float acc[2][4][4];
#pragma unroll
    for (int i = 0; i < 2; ++i)
#pragma unroll
        for (int j = 0; j < 4; ++j)
#pragma unroll
            for (int q = 0; q < 4; ++q) acc[i][j][q] = 0.0f;

    // ldmatrix lane addresses (bytes), k-step adds kk*32B (16 bf16)
    uint32_t aHi[2], aLo[2], bHi[2], bLo[2];
    {
        const uint32_t aBaseHi = smem_u32(sAhi), aBaseLo = smem_u32(sAlo);
        const uint32_t bBaseHi = smem_u32(sWhi), bBaseLo = smem_u32(sWlo);
        int ar = m0 + (lane & 15);
        int ac = (lane >> 4) * 8;
#pragma unroll
        for (int i = 0; i < 2; ++i) {
            uint32_t off = ((ar + 16 * i) * LDS_STRIDE + ac) * 2;
            aHi[i] = aBaseHi + off;
            aLo[i] = aBaseLo + off;
        }
        int br = n0 + ((lane >> 4) << 3) + (lane & 7);
        int bc = ((lane >> 3) & 1) * 8;
#pragma unroll
        for (int j = 0; j < 2; ++j) {
            uint32_t off = ((br + 16 * j) * LDS_STRIDE + bc) * 2;
            bHi[j] = bBaseHi + off;
            bLo[j] = bBaseLo + off;
        }
    }

#pragma unroll
    for (int kk = 0; kk < 8; ++kk) {
        const uint32_t ko = kk * 32;  // 16 bf16 = 32 bytes
        uint32_t ah[2][4], al[2][4], bh[2][4], bl[2][4];
#pragma unroll
        for (int i = 0; i < 2; ++i) { LDSM4(ah[i], aHi[i] + ko); }
#pragma unroll
        for (int j = 0; j < 2; ++j) { LDSM4(bh[j], bHi[j] + ko); }
#pragma unroll
        for (int i = 0; i < 2; ++i) { LDSM4(al[i], aLo[i] + ko); }
#pragma unroll
        for (int j = 0; j < 2; ++j) { LDSM4(bl[j], bLo[j] + ko); }

#pragma unroll
        for (int i = 0; i < 2; ++i) {
#pragma unroll
            for (int jj = 0; jj < 4; ++jj) {
                const int pr = jj >> 1, wh = (jj & 1) * 2;
                MMA16816(acc[i][jj], ah[i], bh[pr][wh], bh[pr][wh + 1]);  // hi*hi
                MMA16816(acc[i][jj], ah[i], bl[pr][wh], bl[pr][wh + 1]);  // hi*lo
                MMA16816(acc[i][jj], al[i], bh[pr][wh], bh[pr][wh + 1]);  // lo*hi
            }
        }
    }

    // epilogue: bias + direct float2 stores
    const int gr = lane >> 2;
    const int gc = (lane & 3) * 2;
#pragma unroll
    for (int jj = 0; jj < 4; ++jj) {
        const int col = bn0 + n0 + jj * 8 + gc;
        const float b0v = bias[col];
        const float b1v = bias[col + 1];
#pragma unroll
        for (int i = 0; i < 2; ++i) {
            const int row = bm0 + m0 + i * 16 + gr;
            float2 o0, o1;
            o0.x = acc[i][jj][0] + b0v; o0.y = acc[i][jj][1] + b1v;
            o1.x = acc[i][jj][2] + b0v; o1.y = acc[i][jj][3] + b1v;
            *reinterpret_cast<float2*>(&C[(size_t)row * NT + col])       = o0;
            *reinterpret_cast<float2*>(&C[(size_t)(row + 8) * NT + col]) = o1;
        }
    }
}

// ---------------- EMA scan + sigmoid gate (one thread per (b,n,4h) chain) ----------------
__global__ __launch_bounds__(256)
void ema_gate_kernel(const float4* __restrict__ expanded, float4* __restrict__ gated) {
    int tid = blockIdx.x * blockDim.x + threadIdx.x;  // 0 .. B*N*32-1
    int h4 = tid & 31;            // float4 index within 128 h
    int n  = (tid >> 5) & (Ndim - 1);
    int b  = tid >> 14;           // N*32 = 16384

    // expanded row stride = 256 floats = 64 float4; gated = 32 float4
    size_t base   = (((size_t)b * Tdim) * Ndim + n) * 64;
    size_t stride = (size_t)Ndim * 64;
    size_t ybase  = (((size_t)b * Tdim) * Ndim + n) * 32;
    size_t ystr   = (size_t)Ndim * 32;

    float4 s = make_float4(0.f, 0.f, 0.f, 0.f);
#pragma unroll 4
    for (int t = 0; t < Tdim; ++t) {
        float4 g = expanded[base + 32 + h4];
        float4 p = expanded[base + h4];
        s.x = fmaf(0.9f, s.x, 0.1f * g.x);
        s.y = fmaf(0.9f, s.y, 0.1f * g.y);
        s.z = fmaf(0.9f, s.z, 0.1f * g.z);
        s.w = fmaf(0.9f, s.w, 0.1f * g.w);
        float4 o;
        o.x = p.x / (1.0f + __expf(-s.x));
        o.y = p.y / (1.0f + __expf(-s.y));
        o.z = p.z / (1.0f + __expf(-s.z));
        o.w = p.w / (1.0f + __expf(-s.w));
        gated[ybase + h4] = o;
        base  += stride;
        ybase += ystr;
    }
}

// ---------------- launch ----------------
extern "C" void kernel_launch(void* const* d_in, const int* in_sizes, int n_in,
                              void* d_out, int out_size) {
    const float* x     = (const float*)d_in[0];  // [B,T,N,H]
    const float* W_exp = (const float*)d_in[1];  // [2H,H]
    const float* b_exp = (const float*)d_in[2];  // [2H]
    const float* W_con = (const float*)d_in[3];  // [H,H]
    const float* b_con = (const float*)d_in[4];  // [H]
    float* out = (float*)d_out;                  // [B,T,N,H]

    float *expanded, *gated;
    cudaGetSymbolAddress((void**)&expanded, g_expanded);
    cudaGetSymbolAddress((void**)&gated, g_gated);

    constexpr int SMEM = 4 * 128 * LDS_STRIDE * 2;  // 139264 bytes
    cudaFuncSetAttribute(mma_gemm<256>, cudaFuncAttributeMaxDynamicSharedMemorySize, SMEM);
    cudaFuncSetAttribute(mma_gemm<128>, cudaFuncAttributeMaxDynamicSharedMemorySize, SMEM);

    // GEMM1: expanded[M,256] = x[M,128] * W_exp^T + b_exp
    {
        dim3 grid(Mrows / 128, 2);
        mma_gemm<256><<<grid, 512, SMEM>>>(x, W_exp, b_exp, expanded);
    }

    // EMA scan + sigmoid gate + primary multiply
    ema_gate_kernel<<<(Bdim * Ndim * 32) / 256, 256>>>(
        (const float4*)expanded, (float4*)gated);

    // GEMM2: out[M,128] = gated[M,128] * W_con^T + b_con
    {
        dim3 grid(Mrows / 128, 1);
        mma_gemm<128><<<grid, 512, SMEM>>>(gated, W_con, b_con, out);
    }
}